// round 3
// baseline (speedup 1.0000x reference)
#include <cuda_runtime.h>
#include <cuda_bf16.h>

#define N_NODES 100000
#define N_EDGES 1600000
#define IN_F    64
#define HID     128
#define N_CLS   10

#define NB_NODES ((N_NODES + 255) / 256)     // 391
#define NB_EDGES (N_EDGES / 256)             // 6250
#define NB_CVT   (N_NODES * IN_F / (256*4))  // 6250

// ---------------- device scratch ----------------
__device__ int   g_deg[N_NODES];
__device__ int   g_ptr[N_NODES + 1];
__device__ int   g_cur[N_NODES];
__device__ float g_dis[N_NODES];
__device__ int   g_srcs[N_EDGES];
__device__ int   g_bsum[NB_NODES];           // per-block degree sums
__device__ int   g_boff[NB_NODES];           // exclusive block offsets
__device__ __nv_bfloat162 g_xh[(size_t)N_NODES * 32];  // x in bf16 (12.8 MB)
__device__ float g_aggx[(size_t)N_NODES * IN_F];       // \hat{A} x (fp32, 25.6 MB)
__device__ float g_z[(size_t)N_NODES * N_CLS];
__device__ float g_part[NB_NODES * 11];

// ---------------- f32x2 helpers (FFMA2) ----------------
__device__ __forceinline__ unsigned long long pack2(float x, float y) {
    unsigned long long r;
    asm("mov.b64 %0, {%1,%2};" : "=l"(r) : "f"(x), "f"(y));
    return r;
}
__device__ __forceinline__ void fma2(unsigned long long& acc, unsigned long long a, unsigned long long b) {
    asm("fma.rn.f32x2 %0, %1, %2, %0;" : "+l"(acc) : "l"(a), "l"(b));
}
__device__ __forceinline__ float2 unpack2(unsigned long long v) {
    float2 f;
    asm("mov.b64 {%0,%1}, %2;" : "=f"(f.x), "=f"(f.y) : "l"(v));
    return f;
}

// ---------------- K1: zero degree histogram ----------------
__global__ void k_init() {
    int i = blockIdx.x * blockDim.x + threadIdx.x;
    if (i < N_NODES) g_deg[i] = 0;
}

// ---------------- K2: fused degree histogram + x->bf16 convert ----------------
__global__ void k_pre(const int* __restrict__ ei, const float* __restrict__ x) {
    int b = blockIdx.x;
    if (b < NB_EDGES) {
        int i = b * 256 + threadIdx.x;               // exactly N_EDGES threads
        int c = ei[N_EDGES + i];
        if ((unsigned)c < (unsigned)N_NODES)
            atomicAdd(&g_deg[c], 1);
    } else {
        int i = (b - NB_EDGES) * 256 + threadIdx.x;  // 1.6M threads, 4 floats each
        float4 v = ((const float4*)x)[i];
        __nv_bfloat162 lo = __floats2bfloat162_rn(v.x, v.y);
        __nv_bfloat162 hi = __floats2bfloat162_rn(v.z, v.w);
        uint2 pk;
        pk.x = *(unsigned int*)&lo;
        pk.y = *(unsigned int*)&hi;
        ((uint2*)g_xh)[i] = pk;
    }
}

// ---------------- K3a: per-block degree sums ----------------
__global__ void k_scan1() {
    const int tid = threadIdx.x, lane = tid & 31, wid = tid >> 5;
    int i = blockIdx.x * 256 + tid;
    int v = (i < N_NODES) ? g_deg[i] : 0;
    #pragma unroll
    for (int o = 16; o > 0; o >>= 1) v += __shfl_xor_sync(0xffffffffu, v, o);
    __shared__ int ws[8];
    if (lane == 0) ws[wid] = v;
    __syncthreads();
    if (tid == 0) {
        int s = 0;
        #pragma unroll
        for (int w = 0; w < 8; w++) s += ws[w];
        g_bsum[blockIdx.x] = s;
    }
}

// ---------------- K3b: scan 391 block sums (1 block, 512 thr) ----------------
__global__ void k_scan2() {
    const int tid = threadIdx.x, lane = tid & 31, wid = tid >> 5;
    int v = (tid < NB_NODES) ? g_bsum[tid] : 0;
    int x = v;
    #pragma unroll
    for (int o = 1; o < 32; o <<= 1) {
        int t = __shfl_up_sync(0xffffffffu, x, o);
        if (lane >= o) x += t;
    }
    __shared__ int ws[16];
    if (lane == 31) ws[wid] = x;
    __syncthreads();
    if (wid == 0 && lane < 16) {
        int t = ws[lane];
        #pragma unroll
        for (int o = 1; o < 16; o <<= 1) {
            int u = __shfl_up_sync(0x0000ffffu, t, o);
            if (lane >= o) t += u;
        }
        ws[lane] = t;
    }
    __syncthreads();
    int incl = x + (wid > 0 ? ws[wid - 1] : 0);
    if (tid < NB_NODES) g_boff[tid] = incl - v;
    if (tid == NB_NODES - 1) g_ptr[N_NODES] = incl;
}

// ---------------- K3c: block-local exclusive scan + finalize ----------------
__global__ void k_scan3() {
    const int tid = threadIdx.x, lane = tid & 31, wid = tid >> 5;
    int i = blockIdx.x * 256 + tid;
    int v = (i < N_NODES) ? g_deg[i] : 0;
    int x = v;
    #pragma unroll
    for (int o = 1; o < 32; o <<= 1) {
        int t = __shfl_up_sync(0xffffffffu, x, o);
        if (lane >= o) x += t;
    }
    __shared__ int ws[8];
    if (lane == 31) ws[wid] = x;
    __syncthreads();
    if (wid == 0 && lane < 8) {
        int t = ws[lane];
        #pragma unroll
        for (int o = 1; o < 8; o <<= 1) {
            int u = __shfl_up_sync(0x000000ffu, t, o);
            if (lane >= o) t += u;
        }
        ws[lane] = t;
    }
    __syncthreads();
    int excl = x - v + (wid > 0 ? ws[wid - 1] : 0) + g_boff[blockIdx.x];
    if (i < N_NODES) {
        g_ptr[i] = excl;
        g_cur[i] = excl;
        g_dis[i] = rsqrtf((float)(v + 1));   // +1 self-loop
    }
}

// ---------------- K4: CSR fill ----------------
__global__ void k_csrfill(const int* __restrict__ ei) {
    int i = blockIdx.x * blockDim.x + threadIdx.x;
    int r = ei[i];
    int c = ei[N_EDGES + i];
    if ((unsigned)c < (unsigned)N_NODES && (unsigned)r < (unsigned)N_NODES) {
        int pos = atomicAdd(&g_cur[c], 1);
        g_srcs[pos] = r;
    }
}

// ---------------- K5: agg = \hat{A} x  (bf16 gather, warp per node) ----------
__global__ void k_aggx() {
    int warp = (blockIdx.x * blockDim.x + threadIdx.x) >> 5;
    int lane = threadIdx.x & 31;
    if (warp >= N_NODES) return;
    float di = g_dis[warp];
    float2 v = __bfloat1622float2(g_xh[(size_t)warp * 32 + lane]);
    float w0 = di * di;
    float2 acc;
    acc.x = w0 * v.x;
    acc.y = w0 * v.y;
    int p = g_ptr[warp], e = g_ptr[warp + 1];
    for (; p + 4 <= e; p += 4) {
        int r0 = g_srcs[p], r1 = g_srcs[p + 1], r2 = g_srcs[p + 2], r3 = g_srcs[p + 3];
        float a0 = g_dis[r0] * di, a1 = g_dis[r1] * di, a2 = g_dis[r2] * di, a3 = g_dis[r3] * di;
        float2 u0 = __bfloat1622float2(g_xh[(size_t)r0 * 32 + lane]);
        float2 u1 = __bfloat1622float2(g_xh[(size_t)r1 * 32 + lane]);
        float2 u2 = __bfloat1622float2(g_xh[(size_t)r2 * 32 + lane]);
        float2 u3 = __bfloat1622float2(g_xh[(size_t)r3 * 32 + lane]);
        acc.x += a0 * u0.x; acc.y += a0 * u0.y;
        acc.x += a1 * u1.x; acc.y += a1 * u1.y;
        acc.x += a2 * u2.x; acc.y += a2 * u2.y;
        acc.x += a3 * u3.x; acc.y += a3 * u3.y;
    }
    for (; p < e; ++p) {
        int r = g_srcs[p];
        float w = g_dis[r] * di;
        float2 u = __bfloat1622float2(g_xh[(size_t)r * 32 + lane]);
        acc.x += w * u.x; acc.y += w * u.y;
    }
    ((float2*)g_aggx)[(size_t)warp * 32 + lane] = acc;
}

// ---------------- K6: fused z = relu(agg @ W1 + b1) @ W2  (f32x2 FFMA2) -----
// Block: 256 thr = 8 warps. Tile 64 rows x 128 cols. Thread (ty,tx):
// row-pairs ty*8+{0,1},{2,3},{4,5},{6,7}; cols tx*4..+3.
// sA is column-major [kk][m] so ld.shared.v2 yields a packed row-pair.
__global__ void __launch_bounds__(256, 2) k_fused_gemm(
    const float* __restrict__ W1, const float* __restrict__ b1,
    const float* __restrict__ W2)
{
    __shared__ __align__(16) float sW1[IN_F * HID];     // 32 KB
    __shared__ __align__(16) float sW2[HID * N_CLS];    // 5 KB
    __shared__ __align__(16) float sA[32 * 66];         // 8.25 KB (col-major, pad 66)

    const int tid = threadIdx.x;
    const int tx = tid & 31, ty = tid >> 5;
    const int row0 = blockIdx.x * 64;

    for (int t = tid; t < IN_F * HID; t += 256) sW1[t] = W1[t];
    for (int t = tid; t < HID * N_CLS; t += 256) sW2[t] = W2[t];

    unsigned long long acc2[4][4];
    #pragma unroll
    for (int q = 0; q < 4; q++)
        #pragma unroll
        for (int j = 0; j < 4; j++) acc2[q][j] = 0ull;

    for (int kb = 0; kb < IN_F; kb += 32) {
        __syncthreads();
        // stage: 64 rows x 32 k, coalesced gmem read, transposed smem write
        for (int t = tid; t < 64 * 32; t += 256) {
            int m = t >> 5, kk = t & 31;
            int gr = row0 + m;
            float v = (gr < N_NODES) ? g_aggx[(size_t)gr * IN_F + kb + kk] : 0.f;
            sA[kk * 66 + m] = v;
        }
        __syncthreads();
        #pragma unroll
        for (int kk = 0; kk < 32; kk++) {
            float4 b = *(const float4*)&sW1[(kb + kk) * HID + tx * 4];
            unsigned long long bb0 = pack2(b.x, b.x);
            unsigned long long bb1 = pack2(b.y, b.y);
            unsigned long long bb2 = pack2(b.z, b.z);
            unsigned long long bb3 = pack2(b.w, b.w);
            #pragma unroll
            for (int q = 0; q < 4; q++) {
                unsigned long long a2 = *(const unsigned long long*)&sA[kk * 66 + ty * 8 + 2 * q];
                fma2(acc2[q][0], a2, bb0);
                fma2(acc2[q][1], a2, bb1);
                fma2(acc2[q][2], a2, bb2);
                fma2(acc2[q][3], a2, bb3);
            }
        }
    }

    // epilogue: +b1, relu, GEMM2 (k split across lanes), butterfly reduce
    float4 b1v = *(const float4*)&b1[tx * 4];
    float w2r[40];
    #pragma unroll
    for (int j = 0; j < 4; j++)
        #pragma unroll
        for (int c = 0; c < N_CLS; c++)
            w2r[j * 10 + c] = sW2[(tx * 4 + j) * N_CLS + c];

    #pragma unroll
    for (int q = 0; q < 4; q++) {
        float2 h0 = unpack2(acc2[q][0]);
        float2 h1 = unpack2(acc2[q][1]);
        float2 h2 = unpack2(acc2[q][2]);
        float2 h3 = unpack2(acc2[q][3]);
        #pragma unroll
        for (int s = 0; s < 2; s++) {
            float e0 = fmaxf((s ? h0.y : h0.x) + b1v.x, 0.f);
            float e1 = fmaxf((s ? h1.y : h1.x) + b1v.y, 0.f);
            float e2 = fmaxf((s ? h2.y : h2.x) + b1v.z, 0.f);
            float e3 = fmaxf((s ? h3.y : h3.x) + b1v.w, 0.f);
            float p[10];
            #pragma unroll
            for (int c = 0; c < N_CLS; c++)
                p[c] = e0 * w2r[c] + e1 * w2r[10 + c] + e2 * w2r[20 + c] + e3 * w2r[30 + c];
            #pragma unroll
            for (int off = 16; off > 0; off >>= 1)
                #pragma unroll
                for (int c = 0; c < N_CLS; c++)
                    p[c] += __shfl_xor_sync(0xffffffffu, p[c], off);
            int gr = row0 + ty * 8 + 2 * q + s;
            if (gr < N_NODES && tx < N_CLS)
                g_z[(size_t)gr * N_CLS + tx] = p[tx];
        }
    }
}

// ---------------- K7: agg z (10-dim), +b2, log_softmax, block partials -------
__global__ void k_final(const float* __restrict__ b2) {
    const int tid = threadIdx.x, lane = tid & 31, wid = tid >> 5;
    int i = blockIdx.x * blockDim.x + tid;
    float vals[11];
    #pragma unroll
    for (int v = 0; v < 11; v++) vals[v] = 0.f;

    if (i < N_NODES) {
        const float2* __restrict__ z2 = (const float2*)g_z;
        float di = g_dis[i];
        float w0 = di * di;
        float a[10];
        #pragma unroll
        for (int q = 0; q < 5; q++) {
            float2 u = z2[(size_t)i * 5 + q];
            a[2 * q] = w0 * u.x;
            a[2 * q + 1] = w0 * u.y;
        }
        int p = g_ptr[i], e = g_ptr[i + 1];
        for (; p + 2 <= e; p += 2) {
            int r0 = g_srcs[p], r1 = g_srcs[p + 1];
            float wA = g_dis[r0] * di, wB = g_dis[r1] * di;
            #pragma unroll
            for (int q = 0; q < 5; q++) {
                float2 uA = z2[(size_t)r0 * 5 + q];
                float2 uB = z2[(size_t)r1 * 5 + q];
                a[2 * q]     += wA * uA.x + wB * uB.x;
                a[2 * q + 1] += wA * uA.y + wB * uB.y;
            }
        }
        for (; p < e; ++p) {
            int r = g_srcs[p];
            float w = g_dis[r] * di;
            #pragma unroll
            for (int q = 0; q < 5; q++) {
                float2 u = z2[(size_t)r * 5 + q];
                a[2 * q]     += w * u.x;
                a[2 * q + 1] += w * u.y;
            }
        }
        float mx = -1e30f;
        #pragma unroll
        for (int c = 0; c < 10; c++) { a[c] += b2[c]; mx = fmaxf(mx, a[c]); }
        float se = 0.f;
        #pragma unroll
        for (int c = 0; c < 10; c++) se += expf(a[c] - mx);
        float lse = mx + logf(se);
        #pragma unroll
        for (int c = 0; c < 10; c++) vals[c] = a[c];
        vals[10] = lse;
    }

    #pragma unroll
    for (int v = 0; v < 11; v++)
        #pragma unroll
        for (int off = 16; off > 0; off >>= 1)
            vals[v] += __shfl_xor_sync(0xffffffffu, vals[v], off);

    __shared__ float sw[8][11];
    if (lane == 0)
        #pragma unroll
        for (int v = 0; v < 11; v++) sw[wid][v] = vals[v];
    __syncthreads();
    if (wid == 0) {
        #pragma unroll
        for (int v = 0; v < 11; v++) {
            float t = (lane < 8) ? sw[lane][v] : 0.f;
            #pragma unroll
            for (int off = 4; off > 0; off >>= 1)
                t += __shfl_xor_sync(0xffffffffu, t, off);
            if (lane == 0) g_part[blockIdx.x * 11 + v] = t;
        }
    }
}

// ---------------- K8: final reduce over block partials -> d_out --------------
__global__ void k_reduce(float* __restrict__ out) {
    const int tid = threadIdx.x, lane = tid & 31, wid = tid >> 5;
    float s[11];
    #pragma unroll
    for (int v = 0; v < 11; v++) {
        float t = 0.f;
        for (int b = tid; b < NB_NODES; b += 256) t += g_part[b * 11 + v];
        s[v] = t;
    }
    #pragma unroll
    for (int v = 0; v < 11; v++)
        #pragma unroll
        for (int off = 16; off > 0; off >>= 1)
            s[v] += __shfl_xor_sync(0xffffffffu, s[v], off);

    __shared__ float sw[8][11];
    __shared__ float tot[11];
    if (lane == 0)
        #pragma unroll
        for (int v = 0; v < 11; v++) sw[wid][v] = s[v];
    __syncthreads();
    if (wid == 0) {
        #pragma unroll
        for (int v = 0; v < 11; v++) {
            float t = (lane < 8) ? sw[lane][v] : 0.f;
            #pragma unroll
            for (int off = 4; off > 0; off >>= 1)
                t += __shfl_xor_sync(0xffffffffu, t, off);
            if (lane == 0) tot[v] = t;
        }
    }
    __syncthreads();
    if (tid < 10) out[tid] = (tot[tid] - tot[10]) * (1.0f / (float)N_NODES);
}

// ---------------- launch ----------------
extern "C" void kernel_launch(void* const* d_in, const int* in_sizes, int n_in,
                              void* d_out, int out_size) {
    const float* x  = (const float*)d_in[0];
    const int*   ei = (const int*)d_in[1];     // edge_index: int32
    const float* W1 = (const float*)d_in[2];
    const float* b1 = (const float*)d_in[3];
    const float* W2 = (const float*)d_in[4];
    const float* b2 = (const float*)d_in[5];
    float* out = (float*)d_out;

    k_init<<<NB_NODES, 256>>>();
    k_pre<<<NB_EDGES + NB_CVT, 256>>>(ei, x);
    k_scan1<<<NB_NODES, 256>>>();
    k_scan2<<<1, 512>>>();
    k_scan3<<<NB_NODES, 256>>>();
    k_csrfill<<<NB_EDGES, 256>>>(ei);
    k_aggx<<<(N_NODES * 32 + 255) / 256, 256>>>();
    k_fused_gemm<<<(N_NODES + 63) / 64, 256>>>(W1, b1, W2);
    k_final<<<NB_NODES, 256>>>(b2);
    k_reduce<<<1, 256>>>(out);
}

// round 4
// speedup vs baseline: 1.4652x; 1.4652x over previous
#include <cuda_runtime.h>
#include <cuda_bf16.h>

#define N_NODES 100000
#define N_EDGES 1600000
#define IN_F    64
#define HID     128
#define N_CLS   10

#define NB_NODES ((N_NODES + 255) / 256)     // 391
#define NB_EDGES (N_EDGES / 256)             // 6250
#define NB_CVT   (N_NODES * IN_F / (256*4))  // 6250

// ---------------- device scratch ----------------
__device__ int   g_deg[N_NODES];
__device__ int   g_ptr[N_NODES + 1];
__device__ int   g_cur[N_NODES];
__device__ float g_dis[N_NODES];
__device__ int   g_srcs[N_EDGES];
__device__ int   g_bsum[NB_NODES];
__device__ __nv_bfloat162 g_xh[(size_t)N_NODES * 32];  // x in bf16 (12.8 MB)
__device__ float g_aggx[(size_t)N_NODES * IN_F];       // \hat{A} x (fp32)
__device__ float g_z[(size_t)N_NODES * N_CLS];
__device__ float g_part[NB_NODES * 11];

// ---------------- K1: zero degree histogram ----------------
__global__ void k_init() {
    int i = blockIdx.x * blockDim.x + threadIdx.x;
    if (i < N_NODES) g_deg[i] = 0;
}

// ---------------- K2: fused degree histogram + x->bf16 convert ----------------
__global__ void k_pre(const int* __restrict__ ei, const float* __restrict__ x) {
    int b = blockIdx.x;
    if (b < NB_EDGES) {
        int i = b * 256 + threadIdx.x;
        int c = ei[N_EDGES + i];
        if ((unsigned)c < (unsigned)N_NODES)
            atomicAdd(&g_deg[c], 1);
    } else {
        int i = (b - NB_EDGES) * 256 + threadIdx.x;
        float4 v = ((const float4*)x)[i];
        __nv_bfloat162 lo = __floats2bfloat162_rn(v.x, v.y);
        __nv_bfloat162 hi = __floats2bfloat162_rn(v.z, v.w);
        uint2 pk;
        pk.x = *(unsigned int*)&lo;
        pk.y = *(unsigned int*)&hi;
        ((uint2*)g_xh)[i] = pk;
    }
}

// ---------------- K3a: per-block degree sums ----------------
__global__ void k_scan1() {
    const int tid = threadIdx.x, lane = tid & 31, wid = tid >> 5;
    int i = blockIdx.x * 256 + tid;
    int v = (i < N_NODES) ? g_deg[i] : 0;
    #pragma unroll
    for (int o = 16; o > 0; o >>= 1) v += __shfl_xor_sync(0xffffffffu, v, o);
    __shared__ int ws[8];
    if (lane == 0) ws[wid] = v;
    __syncthreads();
    if (tid == 0) {
        int s = 0;
        #pragma unroll
        for (int w = 0; w < 8; w++) s += ws[w];
        g_bsum[blockIdx.x] = s;
    }
}

// ---------------- K3b: per-block prefix (self-computed) + local scan + finalize
__global__ void k_scan23() {
    const int tid = threadIdx.x, lane = tid & 31, wid = tid >> 5;
    __shared__ int wpre[8];
    __shared__ int ws[8];
    __shared__ int s_pre;

    // prefix = sum of g_bsum[0 .. blockIdx.x)
    int pre = 0;
    for (int b = tid; b < blockIdx.x; b += 256) pre += g_bsum[b];
    #pragma unroll
    for (int o = 16; o > 0; o >>= 1) pre += __shfl_xor_sync(0xffffffffu, pre, o);
    if (lane == 0) wpre[wid] = pre;
    __syncthreads();
    if (tid == 0) {
        int s = 0;
        #pragma unroll
        for (int w = 0; w < 8; w++) s += wpre[w];
        s_pre = s;
    }
    __syncthreads();
    int prefix = s_pre;

    // block-local exclusive scan of degrees
    int i = blockIdx.x * 256 + tid;
    int v = (i < N_NODES) ? g_deg[i] : 0;
    int x = v;
    #pragma unroll
    for (int o = 1; o < 32; o <<= 1) {
        int t = __shfl_up_sync(0xffffffffu, x, o);
        if (lane >= o) x += t;
    }
    if (lane == 31) ws[wid] = x;
    __syncthreads();
    if (wid == 0 && lane < 8) {
        int t = ws[lane];
        #pragma unroll
        for (int o = 1; o < 8; o <<= 1) {
            int u = __shfl_up_sync(0x000000ffu, t, o);
            if (lane >= o) t += u;
        }
        ws[lane] = t;
    }
    __syncthreads();
    int incl = x + (wid > 0 ? ws[wid - 1] : 0);
    int excl = prefix + incl - v;
    if (i < N_NODES) {
        g_ptr[i] = excl;
        g_cur[i] = excl;
        g_dis[i] = rsqrtf((float)(v + 1));   // +1 self-loop
    }
    if (blockIdx.x == NB_NODES - 1 && tid == 255)
        g_ptr[N_NODES] = prefix + incl;      // total edges
}

// ---------------- K4: CSR fill ----------------
__global__ void k_csrfill(const int* __restrict__ ei) {
    int i = blockIdx.x * blockDim.x + threadIdx.x;
    int r = ei[i];
    int c = ei[N_EDGES + i];
    if ((unsigned)c < (unsigned)N_NODES && (unsigned)r < (unsigned)N_NODES) {
        int pos = atomicAdd(&g_cur[c], 1);
        g_srcs[pos] = r;
    }
}

// ---------------- K5: agg = \hat{A} x  (bf16 gather, warp per node, MLP 8) ---
__global__ void k_aggx() {
    int warp = (blockIdx.x * blockDim.x + threadIdx.x) >> 5;
    int lane = threadIdx.x & 31;
    if (warp >= N_NODES) return;
    float di = g_dis[warp];
    float2 v = __bfloat1622float2(g_xh[(size_t)warp * 32 + lane]);
    float w0 = di * di;
    float2 acc;
    acc.x = w0 * v.x;
    acc.y = w0 * v.y;
    int p = g_ptr[warp], e = g_ptr[warp + 1];
    for (; p + 8 <= e; p += 8) {
        int r[8];
        #pragma unroll
        for (int j = 0; j < 8; j++) r[j] = g_srcs[p + j];
        float2 u[8];
        #pragma unroll
        for (int j = 0; j < 8; j++) u[j] = __bfloat1622float2(g_xh[(size_t)r[j] * 32 + lane]);
        float a[8];
        #pragma unroll
        for (int j = 0; j < 8; j++) a[j] = g_dis[r[j]] * di;
        #pragma unroll
        for (int j = 0; j < 8; j++) { acc.x += a[j] * u[j].x; acc.y += a[j] * u[j].y; }
    }
    for (; p + 2 <= e; p += 2) {
        int r0 = g_srcs[p], r1 = g_srcs[p + 1];
        float2 u0 = __bfloat1622float2(g_xh[(size_t)r0 * 32 + lane]);
        float2 u1 = __bfloat1622float2(g_xh[(size_t)r1 * 32 + lane]);
        float a0 = g_dis[r0] * di, a1 = g_dis[r1] * di;
        acc.x += a0 * u0.x; acc.y += a0 * u0.y;
        acc.x += a1 * u1.x; acc.y += a1 * u1.y;
    }
    if (p < e) {
        int r = g_srcs[p];
        float w = g_dis[r] * di;
        float2 u = __bfloat1622float2(g_xh[(size_t)r * 32 + lane]);
        acc.x += w * u.x; acc.y += w * u.y;
    }
    ((float2*)g_aggx)[(size_t)warp * 32 + lane] = acc;
}

// ---------------- K6: fused z = relu(agg @ W1 + b1) @ W2  (scalar FFMA) -----
__global__ void __launch_bounds__(256, 2) k_fused_gemm(
    const float* __restrict__ W1, const float* __restrict__ b1,
    const float* __restrict__ W2)
{
    __shared__ __align__(16) float sW1[IN_F * HID];     // 32 KB
    __shared__ __align__(16) float sW2[HID * N_CLS];    // 5 KB
    __shared__ float sA[64 * 33];                       // 8.4 KB (padded)

    const int tid = threadIdx.x;
    const int tx = tid & 31, ty = tid >> 5;
    const int row0 = blockIdx.x * 64;

    for (int t = tid; t < IN_F * HID; t += 256) sW1[t] = W1[t];
    for (int t = tid; t < HID * N_CLS; t += 256) sW2[t] = W2[t];

    float acc[8][4];
    #pragma unroll
    for (int m = 0; m < 8; m++)
        #pragma unroll
        for (int j = 0; j < 4; j++) acc[m][j] = 0.f;

    for (int kb = 0; kb < IN_F; kb += 32) {
        __syncthreads();
        for (int t = tid; t < 64 * 32; t += 256) {
            int m = t >> 5, kk = t & 31;
            int gr = row0 + m;
            float v = (gr < N_NODES) ? g_aggx[(size_t)gr * IN_F + kb + kk] : 0.f;
            sA[m * 33 + kk] = v;
        }
        __syncthreads();
        #pragma unroll
        for (int kk = 0; kk < 32; kk++) {
            float4 b = *(const float4*)&sW1[(kb + kk) * HID + tx * 4];
            #pragma unroll
            for (int m = 0; m < 8; m++) {
                float a = sA[(ty * 8 + m) * 33 + kk];   // broadcast
                acc[m][0] += a * b.x;
                acc[m][1] += a * b.y;
                acc[m][2] += a * b.z;
                acc[m][3] += a * b.w;
            }
        }
    }

    float4 b1v = *(const float4*)&b1[tx * 4];
    float w2r[40];
    #pragma unroll
    for (int j = 0; j < 4; j++)
        #pragma unroll
        for (int c = 0; c < N_CLS; c++)
            w2r[j * 10 + c] = sW2[(tx * 4 + j) * N_CLS + c];

    #pragma unroll
    for (int m = 0; m < 8; m++) {
        float h0 = fmaxf(acc[m][0] + b1v.x, 0.f);
        float h1 = fmaxf(acc[m][1] + b1v.y, 0.f);
        float h2 = fmaxf(acc[m][2] + b1v.z, 0.f);
        float h3 = fmaxf(acc[m][3] + b1v.w, 0.f);
        float p[10];
        #pragma unroll
        for (int c = 0; c < N_CLS; c++)
            p[c] = h0 * w2r[c] + h1 * w2r[10 + c] + h2 * w2r[20 + c] + h3 * w2r[30 + c];
        #pragma unroll
        for (int off = 16; off > 0; off >>= 1)
            #pragma unroll
            for (int c = 0; c < N_CLS; c++)
                p[c] += __shfl_xor_sync(0xffffffffu, p[c], off);
        int gr = row0 + ty * 8 + m;
        if (gr < N_NODES && tx < N_CLS)
            g_z[(size_t)gr * N_CLS + tx] = p[tx];
    }
}

// ---------------- K7: agg z (10-dim), +b2, log_softmax, block partials -------
__global__ void k_final(const float* __restrict__ b2) {
    const int tid = threadIdx.x, lane = tid & 31, wid = tid >> 5;
    int i = blockIdx.x * blockDim.x + tid;
    float vals[11];
    #pragma unroll
    for (int v = 0; v < 11; v++) vals[v] = 0.f;

    if (i < N_NODES) {
        const float2* __restrict__ z2 = (const float2*)g_z;
        float di = g_dis[i];
        float w0 = di * di;
        float a[10];
        #pragma unroll
        for (int q = 0; q < 5; q++) {
            float2 u = z2[(size_t)i * 5 + q];
            a[2 * q] = w0 * u.x;
            a[2 * q + 1] = w0 * u.y;
        }
        int p = g_ptr[i], e = g_ptr[i + 1];
        for (; p + 2 <= e; p += 2) {
            int r0 = g_srcs[p], r1 = g_srcs[p + 1];
            float wA = g_dis[r0] * di, wB = g_dis[r1] * di;
            #pragma unroll
            for (int q = 0; q < 5; q++) {
                float2 uA = z2[(size_t)r0 * 5 + q];
                float2 uB = z2[(size_t)r1 * 5 + q];
                a[2 * q]     += wA * uA.x + wB * uB.x;
                a[2 * q + 1] += wA * uA.y + wB * uB.y;
            }
        }
        for (; p < e; ++p) {
            int r = g_srcs[p];
            float w = g_dis[r] * di;
            #pragma unroll
            for (int q = 0; q < 5; q++) {
                float2 u = z2[(size_t)r * 5 + q];
                a[2 * q]     += w * u.x;
                a[2 * q + 1] += w * u.y;
            }
        }
        float mx = -1e30f;
        #pragma unroll
        for (int c = 0; c < 10; c++) { a[c] += b2[c]; mx = fmaxf(mx, a[c]); }
        float se = 0.f;
        #pragma unroll
        for (int c = 0; c < 10; c++) se += expf(a[c] - mx);
        float lse = mx + logf(se);
        #pragma unroll
        for (int c = 0; c < 10; c++) vals[c] = a[c];
        vals[10] = lse;
    }

    #pragma unroll
    for (int v = 0; v < 11; v++)
        #pragma unroll
        for (int off = 16; off > 0; off >>= 1)
            vals[v] += __shfl_xor_sync(0xffffffffu, vals[v], off);

    __shared__ float sw[8][11];
    if (lane == 0)
        #pragma unroll
        for (int v = 0; v < 11; v++) sw[wid][v] = vals[v];
    __syncthreads();
    if (wid == 0) {
        #pragma unroll
        for (int v = 0; v < 11; v++) {
            float t = (lane < 8) ? sw[lane][v] : 0.f;
            #pragma unroll
            for (int off = 4; off > 0; off >>= 1)
                t += __shfl_xor_sync(0xffffffffu, t, off);
            if (lane == 0) g_part[blockIdx.x * 11 + v] = t;
        }
    }
}

// ---------------- K8: final reduce over block partials -> d_out --------------
__global__ void k_reduce(float* __restrict__ out) {
    const int tid = threadIdx.x, lane = tid & 31, wid = tid >> 5;
    float s[11];
    #pragma unroll
    for (int v = 0; v < 11; v++) {
        float t = 0.f;
        for (int b = tid; b < NB_NODES; b += 256) t += g_part[b * 11 + v];
        s[v] = t;
    }
    #pragma unroll
    for (int v = 0; v < 11; v++)
        #pragma unroll
        for (int off = 16; off > 0; off >>= 1)
            s[v] += __shfl_xor_sync(0xffffffffu, s[v], off);

    __shared__ float sw[8][11];
    __shared__ float tot[11];
    if (lane == 0)
        #pragma unroll
        for (int v = 0; v < 11; v++) sw[wid][v] = s[v];
    __syncthreads();
    if (wid == 0) {
        #pragma unroll
        for (int v = 0; v < 11; v++) {
            float t = (lane < 8) ? sw[lane][v] : 0.f;
            #pragma unroll
            for (int off = 4; off > 0; off >>= 1)
                t += __shfl_xor_sync(0xffffffffu, t, off);
            if (lane == 0) tot[v] = t;
        }
    }
    __syncthreads();
    if (tid < 10) out[tid] = (tot[tid] - tot[10]) * (1.0f / (float)N_NODES);
}

// ---------------- launch ----------------
extern "C" void kernel_launch(void* const* d_in, const int* in_sizes, int n_in,
                              void* d_out, int out_size) {
    const float* x  = (const float*)d_in[0];
    const int*   ei = (const int*)d_in[1];     // edge_index: int32
    const float* W1 = (const float*)d_in[2];
    const float* b1 = (const float*)d_in[3];
    const float* W2 = (const float*)d_in[4];
    const float* b2 = (const float*)d_in[5];
    float* out = (float*)d_out;

    k_init<<<NB_NODES, 256>>>();
    k_pre<<<NB_EDGES + NB_CVT, 256>>>(ei, x);
    k_scan1<<<NB_NODES, 256>>>();
    k_scan23<<<NB_NODES, 256>>>();
    k_csrfill<<<NB_EDGES, 256>>>(ei);
    k_aggx<<<(N_NODES * 32 + 255) / 256, 256>>>();
    k_fused_gemm<<<(N_NODES + 63) / 64, 256>>>(W1, b1, W2);
    k_final<<<NB_NODES, 256>>>(b2);
    k_reduce<<<1, 256>>>(out);
}

// round 5
// speedup vs baseline: 2.0816x; 1.4207x over previous
#include <cuda_runtime.h>
#include <cuda_bf16.h>
#include <cstdint>

#define N_NODES 100000
#define N_EDGES 1600000
#define IN_F    64
#define HID     128
#define N_CLS   10

#define NB_NODES ((N_NODES + 255) / 256)     // 391
#define NB_EDGES (N_EDGES / 256)             // 6250
#define NB_CVT   (N_NODES * IN_F / (256*4))  // 6250
#define NB_W1    16                          // 32*128 / 256
#define NB_W2    4                           // 64*16 / 256

#define MLP_BLOCKS ((N_NODES + 127) / 128)   // 782

// ---------------- device scratch ----------------
__device__ int      g_deg[N_NODES];
__device__ int      g_ptr[N_NODES + 1];
__device__ int      g_cur[N_NODES];
__device__ float    g_dis[N_NODES];
__device__ int      g_srcs[N_EDGES];
__device__ int      g_bsum[NB_NODES];
__device__ unsigned g_xh[(size_t)N_NODES * 32];    // x bf16x2 (12.8 MB)
__device__ unsigned g_aggh[(size_t)N_NODES * 32];  // \hat{A}x bf16x2 (12.8 MB)
__device__ unsigned g_w1p[32 * 128];               // W1 k-pair packed bf16x2 [k/2][n]
__device__ unsigned g_w2p[64 * 16];                // W2 k-pair packed bf16x2 [k/2][n] (n pad 16)
__device__ float    g_z[(size_t)N_NODES * N_CLS];
__device__ float    g_part[NB_NODES * 11];

__device__ __forceinline__ unsigned packbf(float a, float b) {
    __nv_bfloat162 t = __floats2bfloat162_rn(a, b);
    return *(unsigned*)&t;
}
__device__ __forceinline__ float2 unpackbf(unsigned u) {
    return __bfloat1622float2(*(__nv_bfloat162*)&u);
}
__device__ __forceinline__ uint32_t su32(const void* p) {
    return (uint32_t)__cvta_generic_to_shared(p);
}
__device__ __forceinline__ void ldmatrix4(uint32_t& a0, uint32_t& a1, uint32_t& a2, uint32_t& a3, uint32_t addr) {
    asm volatile("ldmatrix.sync.aligned.m8n8.x4.shared.b16 {%0,%1,%2,%3}, [%4];"
                 : "=r"(a0), "=r"(a1), "=r"(a2), "=r"(a3) : "r"(addr));
}
__device__ __forceinline__ void mma16816(float* c, uint32_t a0, uint32_t a1, uint32_t a2, uint32_t a3,
                                         uint32_t b0, uint32_t b1) {
    asm volatile("mma.sync.aligned.m16n8k16.row.col.f32.bf16.bf16.f32 "
                 "{%0,%1,%2,%3},{%4,%5,%6,%7},{%8,%9},{%0,%1,%2,%3};"
                 : "+f"(c[0]), "+f"(c[1]), "+f"(c[2]), "+f"(c[3])
                 : "r"(a0), "r"(a1), "r"(a2), "r"(a3), "r"(b0), "r"(b1));
}

// ---------------- K1: zero degree histogram ----------------
__global__ void k_init() {
    int i = blockIdx.x * blockDim.x + threadIdx.x;
    if (i < N_NODES) g_deg[i] = 0;
}

// ---------------- K2: fused histogram + x->bf16 + W pack ----------------
__global__ void k_pre(const int* __restrict__ ei, const float* __restrict__ x,
                      const float* __restrict__ W1, const float* __restrict__ W2) {
    int b = blockIdx.x;
    if (b < NB_EDGES) {
        int i = b * 256 + threadIdx.x;
        int c = ei[N_EDGES + i];
        if ((unsigned)c < (unsigned)N_NODES)
            atomicAdd(&g_deg[c], 1);
    } else if (b < NB_EDGES + NB_CVT) {
        int i = (b - NB_EDGES) * 256 + threadIdx.x;
        float4 v = ((const float4*)x)[i];
        uint2 pk;
        pk.x = packbf(v.x, v.y);
        pk.y = packbf(v.z, v.w);
        ((uint2*)g_xh)[i] = pk;
    } else if (b < NB_EDGES + NB_CVT + NB_W1) {
        int t = (b - NB_EDGES - NB_CVT) * 256 + threadIdx.x;   // < 32*128
        int k2 = t >> 7, n = t & 127;
        g_w1p[t] = packbf(W1[(2 * k2) * HID + n], W1[(2 * k2 + 1) * HID + n]);
    } else {
        int t = (b - NB_EDGES - NB_CVT - NB_W1) * 256 + threadIdx.x;  // < 64*16
        int k2 = t >> 4, n = t & 15;
        unsigned v = 0;
        if (n < N_CLS)
            v = packbf(W2[(2 * k2) * N_CLS + n], W2[(2 * k2 + 1) * N_CLS + n]);
        g_w2p[t] = v;
    }
}

// ---------------- K3a: per-block degree sums ----------------
__global__ void k_scan1() {
    const int tid = threadIdx.x, lane = tid & 31, wid = tid >> 5;
    int i = blockIdx.x * 256 + tid;
    int v = (i < N_NODES) ? g_deg[i] : 0;
    #pragma unroll
    for (int o = 16; o > 0; o >>= 1) v += __shfl_xor_sync(0xffffffffu, v, o);
    __shared__ int ws[8];
    if (lane == 0) ws[wid] = v;
    __syncthreads();
    if (tid == 0) {
        int s = 0;
        #pragma unroll
        for (int w = 0; w < 8; w++) s += ws[w];
        g_bsum[blockIdx.x] = s;
    }
}

// ---------------- K3b: per-block prefix + local scan + finalize ----------------
__global__ void k_scan23() {
    const int tid = threadIdx.x, lane = tid & 31, wid = tid >> 5;
    __shared__ int wpre[8];
    __shared__ int ws[8];
    __shared__ int s_pre;

    int pre = 0;
    for (int b = tid; b < blockIdx.x; b += 256) pre += g_bsum[b];
    #pragma unroll
    for (int o = 16; o > 0; o >>= 1) pre += __shfl_xor_sync(0xffffffffu, pre, o);
    if (lane == 0) wpre[wid] = pre;
    __syncthreads();
    if (tid == 0) {
        int s = 0;
        #pragma unroll
        for (int w = 0; w < 8; w++) s += wpre[w];
        s_pre = s;
    }
    __syncthreads();
    int prefix = s_pre;

    int i = blockIdx.x * 256 + tid;
    int v = (i < N_NODES) ? g_deg[i] : 0;
    int x = v;
    #pragma unroll
    for (int o = 1; o < 32; o <<= 1) {
        int t = __shfl_up_sync(0xffffffffu, x, o);
        if (lane >= o) x += t;
    }
    if (lane == 31) ws[wid] = x;
    __syncthreads();
    if (wid == 0 && lane < 8) {
        int t = ws[lane];
        #pragma unroll
        for (int o = 1; o < 8; o <<= 1) {
            int u = __shfl_up_sync(0x000000ffu, t, o);
            if (lane >= o) t += u;
        }
        ws[lane] = t;
    }
    __syncthreads();
    int incl = x + (wid > 0 ? ws[wid - 1] : 0);
    int excl = prefix + incl - v;
    if (i < N_NODES) {
        g_ptr[i] = excl;
        g_cur[i] = excl;
        g_dis[i] = rsqrtf((float)(v + 1));
    }
    if (blockIdx.x == NB_NODES - 1 && tid == 255)
        g_ptr[N_NODES] = prefix + incl;
}

// ---------------- K4: CSR fill ----------------
__global__ void k_csrfill(const int* __restrict__ ei) {
    int i = blockIdx.x * blockDim.x + threadIdx.x;
    int r = ei[i];
    int c = ei[N_EDGES + i];
    if ((unsigned)c < (unsigned)N_NODES && (unsigned)r < (unsigned)N_NODES) {
        int pos = atomicAdd(&g_cur[c], 1);
        g_srcs[pos] = r;
    }
}

// ---------------- K5: agg = \hat{A} x (bf16 gather, fp32 accum, bf16 out) ----
__global__ void k_aggx() {
    int warp = (blockIdx.x * blockDim.x + threadIdx.x) >> 5;
    int lane = threadIdx.x & 31;
    if (warp >= N_NODES) return;
    float di = g_dis[warp];
    float2 v = unpackbf(g_xh[(size_t)warp * 32 + lane]);
    float w0 = di * di;
    float2 acc;
    acc.x = w0 * v.x;
    acc.y = w0 * v.y;
    int p = g_ptr[warp], e = g_ptr[warp + 1];
    for (; p + 8 <= e; p += 8) {
        int r[8];
        #pragma unroll
        for (int j = 0; j < 8; j++) r[j] = g_srcs[p + j];
        float2 u[8];
        #pragma unroll
        for (int j = 0; j < 8; j++) u[j] = unpackbf(g_xh[(size_t)r[j] * 32 + lane]);
        float a[8];
        #pragma unroll
        for (int j = 0; j < 8; j++) a[j] = g_dis[r[j]] * di;
        #pragma unroll
        for (int j = 0; j < 8; j++) { acc.x += a[j] * u[j].x; acc.y += a[j] * u[j].y; }
    }
    for (; p + 2 <= e; p += 2) {
        int r0 = g_srcs[p], r1 = g_srcs[p + 1];
        float2 u0 = unpackbf(g_xh[(size_t)r0 * 32 + lane]);
        float2 u1 = unpackbf(g_xh[(size_t)r1 * 32 + lane]);
        float a0 = g_dis[r0] * di, a1 = g_dis[r1] * di;
        acc.x += a0 * u0.x; acc.y += a0 * u0.y;
        acc.x += a1 * u1.x; acc.y += a1 * u1.y;
    }
    if (p < e) {
        int r = g_srcs[p];
        float w = g_dis[r] * di;
        float2 u = unpackbf(g_xh[(size_t)r * 32 + lane]);
        acc.x += w * u.x; acc.y += w * u.y;
    }
    g_aggh[(size_t)warp * 32 + lane] = packbf(acc.x, acc.y);
}

// ---------------- K6: tensor-core MLP: z = relu(agg@W1+b1)@W2 ----------------
// 128-row tile per block, 8 warps, warp w owns rows w*16..+15.
// GEMM1: A (16x64 bf16, ldmatrix) x W1-frags (smem, conflict-free) -> 16x128 fp32
// epilogue: +b1, relu, bf16 -> smem h; GEMM2: h x W2-frags -> 16x16, write 10 cols.
#define SA_STRIDE 136                        // bf16 units; 272B rows, LDSM conflict-free
#define W1_STRIDE 136                        // u32 units; 136 % 32 == 8 -> conflict-free
#define W2_STRIDE 40                         // u32 units; 40 % 32 == 8
#define SMEM_MLP ((32*W1_STRIDE + 64*W2_STRIDE + 128) * 4 + 128 * SA_STRIDE * 2)

__global__ void __launch_bounds__(256) k_mlp(const float* __restrict__ b1) {
    extern __shared__ __align__(16) unsigned char smem_raw[];
    unsigned* sW1p = (unsigned*)smem_raw;                // 32 x 136
    unsigned* sW2p = sW1p + 32 * W1_STRIDE;              // 64 x 40
    float*    sb1  = (float*)(sW2p + 64 * W2_STRIDE);    // 128
    __nv_bfloat16* sAh = (__nv_bfloat16*)(sb1 + 128);    // 128 x 136 (A tile, then h tile)

    const int tid = threadIdx.x;
    const int w = tid >> 5, l = tid & 31;
    const int row0 = blockIdx.x * 128;

    for (int t = tid; t < 32 * 128; t += 256)
        sW1p[(t >> 7) * W1_STRIDE + (t & 127)] = g_w1p[t];
    for (int t = tid; t < 64 * 16; t += 256)
        sW2p[(t >> 4) * W2_STRIDE + (t & 15)] = g_w2p[t];
    if (tid < 128) sb1[tid] = b1[tid];
    // stage A: 128 rows x 64 bf16 (128B rows = 8 x uint4)
    for (int t = tid; t < 1024; t += 256) {
        int row = t >> 3, q = t & 7;
        int gr = row0 + row;
        uint4 v = make_uint4(0, 0, 0, 0);
        if (gr < N_NODES) v = ((const uint4*)g_aggh)[(size_t)gr * 8 + q];
        *(uint4*)((char*)sAh + row * (SA_STRIDE * 2) + q * 16) = v;
    }
    __syncthreads();

    const int lrow = l >> 2;            // 0..7
    const int colb = (l & 3) * 2;       // 0,2,4,6
    const int nb = l >> 2;              // B-frag n = nt*8 + nb
    const uint32_t a_base = su32(sAh) + (uint32_t)(((w * 16 + (l & 15)) * SA_STRIDE + ((l >> 4) * 8)) * 2);

    float acc[16][4];
    #pragma unroll
    for (int nt = 0; nt < 16; nt++)
        #pragma unroll
        for (int j = 0; j < 4; j++) acc[nt][j] = 0.f;

    #pragma unroll
    for (int kk = 0; kk < 4; kk++) {
        uint32_t a0, a1, a2, a3;
        ldmatrix4(a0, a1, a2, a3, a_base + kk * 32);     // 16 bf16 cols = 32B
        int k2b = kk * 8 + (l & 3);
        #pragma unroll
        for (int nt = 0; nt < 16; nt++) {
            unsigned bf0 = sW1p[k2b * W1_STRIDE + nt * 8 + nb];
            unsigned bf1 = sW1p[(k2b + 4) * W1_STRIDE + nt * 8 + nb];
            mma16816(acc[nt], a0, a1, a2, a3, bf0, bf1);
        }
    }
    __syncthreads();   // all warps done reading A tile before overwrite with h

    // epilogue 1: bias + relu -> bf16 h tile (each warp writes its own 16 rows)
    const int hrow0 = w * 16 + lrow;
    #pragma unroll
    for (int nt = 0; nt < 16; nt++) {
        float bb0 = sb1[nt * 8 + colb];
        float bb1 = sb1[nt * 8 + colb + 1];
        float c0 = fmaxf(acc[nt][0] + bb0, 0.f);
        float c1 = fmaxf(acc[nt][1] + bb1, 0.f);
        float c2 = fmaxf(acc[nt][2] + bb0, 0.f);
        float c3 = fmaxf(acc[nt][3] + bb1, 0.f);
        *(unsigned*)((char*)sAh + (hrow0 * SA_STRIDE + nt * 8 + colb) * 2) = packbf(c0, c1);
        *(unsigned*)((char*)sAh + ((hrow0 + 8) * SA_STRIDE + nt * 8 + colb) * 2) = packbf(c2, c3);
    }
    __syncwarp();

    // GEMM2: h (16x128) x W2 (128x16) -> 16x16
    float acc2[2][4];
    #pragma unroll
    for (int nt = 0; nt < 2; nt++)
        #pragma unroll
        for (int j = 0; j < 4; j++) acc2[nt][j] = 0.f;

    #pragma unroll
    for (int kk = 0; kk < 8; kk++) {
        uint32_t a0, a1, a2, a3;
        ldmatrix4(a0, a1, a2, a3, a_base + kk * 32);
        int k2b = kk * 8 + (l & 3);
        #pragma unroll
        for (int nt = 0; nt < 2; nt++) {
            unsigned bf0 = sW2p[k2b * W2_STRIDE + nt * 8 + nb];
            unsigned bf1 = sW2p[(k2b + 4) * W2_STRIDE + nt * 8 + nb];
            mma16816(acc2[nt], a0, a1, a2, a3, bf0, bf1);
        }
    }

    // write z (cols 0..9)
    int gr0 = row0 + w * 16 + lrow;
    int gr1 = gr0 + 8;
    if (gr0 < N_NODES)
        *(float2*)&g_z[(size_t)gr0 * N_CLS + colb] = make_float2(acc2[0][0], acc2[0][1]);
    if (gr1 < N_NODES)
        *(float2*)&g_z[(size_t)gr1 * N_CLS + colb] = make_float2(acc2[0][2], acc2[0][3]);
    if (colb == 0) {   // cols 8,9
        if (gr0 < N_NODES)
            *(float2*)&g_z[(size_t)gr0 * N_CLS + 8] = make_float2(acc2[1][0], acc2[1][1]);
        if (gr1 < N_NODES)
            *(float2*)&g_z[(size_t)gr1 * N_CLS + 8] = make_float2(acc2[1][2], acc2[1][3]);
    }
}

// ---------------- K7: agg z (10-dim), +b2, log_softmax, block partials -------
__global__ void k_final(const float* __restrict__ b2) {
    const int tid = threadIdx.x, lane = tid & 31, wid = tid >> 5;
    int i = blockIdx.x * blockDim.x + tid;
    float vals[11];
    #pragma unroll
    for (int v = 0; v < 11; v++) vals[v] = 0.f;

    if (i < N_NODES) {
        const float2* __restrict__ z2 = (const float2*)g_z;
        float di = g_dis[i];
        float w0 = di * di;
        float a[10];
        #pragma unroll
        for (int q = 0; q < 5; q++) {
            float2 u = z2[(size_t)i * 5 + q];
            a[2 * q] = w0 * u.x;
            a[2 * q + 1] = w0 * u.y;
        }
        int p = g_ptr[i], e = g_ptr[i + 1];
        for (; p + 2 <= e; p += 2) {
            int r0 = g_srcs[p], r1 = g_srcs[p + 1];
            float wA = g_dis[r0] * di, wB = g_dis[r1] * di;
            #pragma unroll
            for (int q = 0; q < 5; q++) {
                float2 uA = z2[(size_t)r0 * 5 + q];
                float2 uB = z2[(size_t)r1 * 5 + q];
                a[2 * q]     += wA * uA.x + wB * uB.x;
                a[2 * q + 1] += wA * uA.y + wB * uB.y;
            }
        }
        for (; p < e; ++p) {
            int r = g_srcs[p];
            float w = g_dis[r] * di;
            #pragma unroll
            for (int q = 0; q < 5; q++) {
                float2 u = z2[(size_t)r * 5 + q];
                a[2 * q]     += w * u.x;
                a[2 * q + 1] += w * u.y;
            }
        }
        float mx = -1e30f;
        #pragma unroll
        for (int c = 0; c < 10; c++) { a[c] += b2[c]; mx = fmaxf(mx, a[c]); }
        float se = 0.f;
        #pragma unroll
        for (int c = 0; c < 10; c++) se += expf(a[c] - mx);
        float lse = mx + logf(se);
        #pragma unroll
        for (int c = 0; c < 10; c++) vals[c] = a[c];
        vals[10] = lse;
    }

    #pragma unroll
    for (int v = 0; v < 11; v++)
        #pragma unroll
        for (int off = 16; off > 0; off >>= 1)
            vals[v] += __shfl_xor_sync(0xffffffffu, vals[v], off);

    __shared__ float sw[8][11];
    if (lane == 0)
        #pragma unroll
        for (int v = 0; v < 11; v++) sw[wid][v] = vals[v];
    __syncthreads();
    if (wid == 0) {
        #pragma unroll
        for (int v = 0; v < 11; v++) {
            float t = (lane < 8) ? sw[lane][v] : 0.f;
            #pragma unroll
            for (int off = 4; off > 0; off >>= 1)
                t += __shfl_xor_sync(0xffffffffu, t, off);
            if (lane == 0) g_part[blockIdx.x * 11 + v] = t;
        }
    }
}

// ---------------- K8: final reduce over block partials -> d_out --------------
__global__ void k_reduce(float* __restrict__ out) {
    const int tid = threadIdx.x, lane = tid & 31, wid = tid >> 5;
    float s[11];
    #pragma unroll
    for (int v = 0; v < 11; v++) {
        float t = 0.f;
        for (int b = tid; b < NB_NODES; b += 256) t += g_part[b * 11 + v];
        s[v] = t;
    }
    #pragma unroll
    for (int v = 0; v < 11; v++)
        #pragma unroll
        for (int off = 16; off > 0; off >>= 1)
            s[v] += __shfl_xor_sync(0xffffffffu, s[v], off);

    __shared__ float sw[8][11];
    __shared__ float tot[11];
    if (lane == 0)
        #pragma unroll
        for (int v = 0; v < 11; v++) sw[wid][v] = s[v];
    __syncthreads();
    if (wid == 0) {
        #pragma unroll
        for (int v = 0; v < 11; v++) {
            float t = (lane < 8) ? sw[lane][v] : 0.f;
            #pragma unroll
            for (int off = 4; off > 0; off >>= 1)
                t += __shfl_xor_sync(0xffffffffu, t, off);
            if (lane == 0) tot[v] = t;
        }
    }
    __syncthreads();
    if (tid < 10) out[tid] = (tot[tid] - tot[10]) * (1.0f / (float)N_NODES);
}

// ---------------- launch ----------------
extern "C" void kernel_launch(void* const* d_in, const int* in_sizes, int n_in,
                              void* d_out, int out_size) {
    const float* x  = (const float*)d_in[0];
    const int*   ei = (const int*)d_in[1];     // edge_index: int32
    const float* W1 = (const float*)d_in[2];
    const float* b1 = (const float*)d_in[3];
    const float* W2 = (const float*)d_in[4];
    const float* b2 = (const float*)d_in[5];
    float* out = (float*)d_out;

    cudaFuncSetAttribute(k_mlp, cudaFuncAttributeMaxDynamicSharedMemorySize, SMEM_MLP);

    k_init<<<NB_NODES, 256>>>();
    k_pre<<<NB_EDGES + NB_CVT + NB_W1 + NB_W2, 256>>>(ei, x, W1, W2);
    k_scan1<<<NB_NODES, 256>>>();
    k_scan23<<<NB_NODES, 256>>>();
    k_csrfill<<<NB_EDGES, 256>>>(ei);
    k_aggx<<<(N_NODES * 32 + 255) / 256, 256>>>();
    k_mlp<<<MLP_BLOCKS, 256, SMEM_MLP>>>(b1);
    k_final<<<NB_NODES, 256>>>(b2);
    k_reduce<<<1, 256>>>(out);
}

// round 6
// speedup vs baseline: 2.2237x; 1.0683x over previous
#include <cuda_runtime.h>
#include <cuda_bf16.h>
#include <cstdint>

#define N_NODES 100000
#define N_EDGES 1600000
#define IN_F    64
#define HID     128
#define N_CLS   10

#define NB_NODES ((N_NODES + 255) / 256)     // 391
#define NB_EDGES (N_EDGES / 256)             // 6250
#define NB_CVT   (N_NODES * IN_F / (256*4))  // 6250
#define NB_W1    16                          // 32*128 / 256
#define NB_W2    4                           // 64*16 / 256

#define MLP_BLOCKS ((N_NODES + 127) / 128)   // 782

// ---------------- device scratch ----------------
__device__ int      g_deg[N_NODES];          // zero-init; re-zeroed by k_csrfill
__device__ int      g_ptr[N_NODES + 1];
__device__ int      g_cur[N_NODES];
__device__ float    g_dis[N_NODES];
__device__ int      g_srcs[N_EDGES];
__device__ int      g_bsum[NB_NODES];
__device__ unsigned g_xh[(size_t)N_NODES * 32];    // x bf16x2 (12.8 MB)
__device__ unsigned g_aggh[(size_t)N_NODES * 32];  // \hat{A}x bf16x2 (12.8 MB)
__device__ unsigned g_w1p[32 * 128];               // W1 k-pair packed bf16x2
__device__ unsigned g_w2p[64 * 16];                // W2 k-pair packed bf16x2 (n pad 16)
__device__ unsigned g_zh[(size_t)N_NODES * 8];     // z bf16, 16 cols padded (3.2 MB)
__device__ float    g_part[NB_NODES * 11];
__device__ unsigned g_done;                        // zero-init; reset by last block

__device__ __forceinline__ unsigned packbf(float a, float b) {
    __nv_bfloat162 t = __floats2bfloat162_rn(a, b);
    return *(unsigned*)&t;
}
__device__ __forceinline__ float2 unpackbf(unsigned u) {
    return __bfloat1622float2(*(__nv_bfloat162*)&u);
}
__device__ __forceinline__ uint32_t su32(const void* p) {
    return (uint32_t)__cvta_generic_to_shared(p);
}
__device__ __forceinline__ void ldmatrix4(uint32_t& a0, uint32_t& a1, uint32_t& a2, uint32_t& a3, uint32_t addr) {
    asm volatile("ldmatrix.sync.aligned.m8n8.x4.shared.b16 {%0,%1,%2,%3}, [%4];"
                 : "=r"(a0), "=r"(a1), "=r"(a2), "=r"(a3) : "r"(addr));
}
__device__ __forceinline__ void mma16816(float* c, uint32_t a0, uint32_t a1, uint32_t a2, uint32_t a3,
                                         uint32_t b0, uint32_t b1) {
    asm volatile("mma.sync.aligned.m16n8k16.row.col.f32.bf16.bf16.f32 "
                 "{%0,%1,%2,%3},{%4,%5,%6,%7},{%8,%9},{%0,%1,%2,%3};"
                 : "+f"(c[0]), "+f"(c[1]), "+f"(c[2]), "+f"(c[3])
                 : "r"(a0), "r"(a1), "r"(a2), "r"(a3), "r"(b0), "r"(b1));
}

// ---------------- K2: fused histogram + x->bf16 + W pack ----------------
__global__ void k_pre(const int* __restrict__ ei, const float* __restrict__ x,
                      const float* __restrict__ W1, const float* __restrict__ W2) {
    int b = blockIdx.x;
    if (b < NB_EDGES) {
        int i = b * 256 + threadIdx.x;
        int c = ei[N_EDGES + i];
        if ((unsigned)c < (unsigned)N_NODES)
            atomicAdd(&g_deg[c], 1);
    } else if (b < NB_EDGES + NB_CVT) {
        int i = (b - NB_EDGES) * 256 + threadIdx.x;
        float4 v = ((const float4*)x)[i];
        uint2 pk;
        pk.x = packbf(v.x, v.y);
        pk.y = packbf(v.z, v.w);
        ((uint2*)g_xh)[i] = pk;
    } else if (b < NB_EDGES + NB_CVT + NB_W1) {
        int t = (b - NB_EDGES - NB_CVT) * 256 + threadIdx.x;   // < 32*128
        int k2 = t >> 7, n = t & 127;
        g_w1p[t] = packbf(W1[(2 * k2) * HID + n], W1[(2 * k2 + 1) * HID + n]);
    } else {
        int t = (b - NB_EDGES - NB_CVT - NB_W1) * 256 + threadIdx.x;  // < 64*16
        int k2 = t >> 4, n = t & 15;
        unsigned v = 0;
        if (n < N_CLS)
            v = packbf(W2[(2 * k2) * N_CLS + n], W2[(2 * k2 + 1) * N_CLS + n]);
        g_w2p[t] = v;
    }
}

// ---------------- K3a: per-block degree sums ----------------
__global__ void k_scan1() {
    const int tid = threadIdx.x, lane = tid & 31, wid = tid >> 5;
    int i = blockIdx.x * 256 + tid;
    int v = (i < N_NODES) ? g_deg[i] : 0;
    #pragma unroll
    for (int o = 16; o > 0; o >>= 1) v += __shfl_xor_sync(0xffffffffu, v, o);
    __shared__ int ws[8];
    if (lane == 0) ws[wid] = v;
    __syncthreads();
    if (tid == 0) {
        int s = 0;
        #pragma unroll
        for (int w = 0; w < 8; w++) s += ws[w];
        g_bsum[blockIdx.x] = s;
    }
}

// ---------------- K3b: per-block prefix + local scan + finalize ----------------
__global__ void k_scan23() {
    const int tid = threadIdx.x, lane = tid & 31, wid = tid >> 5;
    __shared__ int wpre[8];
    __shared__ int ws[8];
    __shared__ int s_pre;

    int pre = 0;
    for (int b = tid; b < blockIdx.x; b += 256) pre += g_bsum[b];
    #pragma unroll
    for (int o = 16; o > 0; o >>= 1) pre += __shfl_xor_sync(0xffffffffu, pre, o);
    if (lane == 0) wpre[wid] = pre;
    __syncthreads();
    if (tid == 0) {
        int s = 0;
        #pragma unroll
        for (int w = 0; w < 8; w++) s += wpre[w];
        s_pre = s;
    }
    __syncthreads();
    int prefix = s_pre;

    int i = blockIdx.x * 256 + tid;
    int v = (i < N_NODES) ? g_deg[i] : 0;
    int x = v;
    #pragma unroll
    for (int o = 1; o < 32; o <<= 1) {
        int t = __shfl_up_sync(0xffffffffu, x, o);
        if (lane >= o) x += t;
    }
    if (lane == 31) ws[wid] = x;
    __syncthreads();
    if (wid == 0 && lane < 8) {
        int t = ws[lane];
        #pragma unroll
        for (int o = 1; o < 8; o <<= 1) {
            int u = __shfl_up_sync(0x000000ffu, t, o);
            if (lane >= o) t += u;
        }
        ws[lane] = t;
    }
    __syncthreads();
    int incl = x + (wid > 0 ? ws[wid - 1] : 0);
    int excl = prefix + incl - v;
    if (i < N_NODES) {
        g_ptr[i] = excl;
        g_cur[i] = excl;
        g_dis[i] = rsqrtf((float)(v + 1));
    }
    if (blockIdx.x == NB_NODES - 1 && tid == 255)
        g_ptr[N_NODES] = prefix + incl;
}

// ---------------- K4: CSR fill (+ g_deg reset for next call) ----------------
__global__ void k_csrfill(const int* __restrict__ ei) {
    int i = blockIdx.x * blockDim.x + threadIdx.x;
    if (i < N_NODES) g_deg[i] = 0;   // last reader (k_scan23) already ran
    int r = ei[i];
    int c = ei[N_EDGES + i];
    if ((unsigned)c < (unsigned)N_NODES && (unsigned)r < (unsigned)N_NODES) {
        int pos = atomicAdd(&g_cur[c], 1);
        g_srcs[pos] = r;
    }
}

// ---------------- K5: agg = \hat{A} x (bf16 gather, fp32 accum, bf16 out) ----
__global__ void k_aggx() {
    int warp = (blockIdx.x * blockDim.x + threadIdx.x) >> 5;
    int lane = threadIdx.x & 31;
    if (warp >= N_NODES) return;
    float di = g_dis[warp];
    float2 v = unpackbf(g_xh[(size_t)warp * 32 + lane]);
    float w0 = di * di;
    float2 acc;
    acc.x = w0 * v.x;
    acc.y = w0 * v.y;
    int p = g_ptr[warp], e = g_ptr[warp + 1];
    for (; p + 8 <= e; p += 8) {
        int r[8];
        #pragma unroll
        for (int j = 0; j < 8; j++) r[j] = g_srcs[p + j];
        float2 u[8];
        #pragma unroll
        for (int j = 0; j < 8; j++) u[j] = unpackbf(g_xh[(size_t)r[j] * 32 + lane]);
        float a[8];
        #pragma unroll
        for (int j = 0; j < 8; j++) a[j] = g_dis[r[j]] * di;
        #pragma unroll
        for (int j = 0; j < 8; j++) { acc.x += a[j] * u[j].x; acc.y += a[j] * u[j].y; }
    }
    for (; p + 2 <= e; p += 2) {
        int r0 = g_srcs[p], r1 = g_srcs[p + 1];
        float2 u0 = unpackbf(g_xh[(size_t)r0 * 32 + lane]);
        float2 u1 = unpackbf(g_xh[(size_t)r1 * 32 + lane]);
        float a0 = g_dis[r0] * di, a1 = g_dis[r1] * di;
        acc.x += a0 * u0.x; acc.y += a0 * u0.y;
        acc.x += a1 * u1.x; acc.y += a1 * u1.y;
    }
    if (p < e) {
        int r = g_srcs[p];
        float w = g_dis[r] * di;
        float2 u = unpackbf(g_xh[(size_t)r * 32 + lane]);
        acc.x += w * u.x; acc.y += w * u.y;
    }
    g_aggh[(size_t)warp * 32 + lane] = packbf(acc.x, acc.y);
}

// ---------------- K6: tensor-core MLP: z = relu(agg@W1+b1)@W2 ----------------
#define SA_STRIDE 136
#define W1_STRIDE 136
#define W2_STRIDE 40
#define SMEM_MLP ((32*W1_STRIDE + 64*W2_STRIDE + 128) * 4 + 128 * SA_STRIDE * 2)

__global__ void __launch_bounds__(256) k_mlp(const float* __restrict__ b1) {
    extern __shared__ __align__(16) unsigned char smem_raw[];
    unsigned* sW1p = (unsigned*)smem_raw;                // 32 x 136
    unsigned* sW2p = sW1p + 32 * W1_STRIDE;              // 64 x 40
    float*    sb1  = (float*)(sW2p + 64 * W2_STRIDE);    // 128
    __nv_bfloat16* sAh = (__nv_bfloat16*)(sb1 + 128);    // 128 x 136

    const int tid = threadIdx.x;
    const int w = tid >> 5, l = tid & 31;
    const int row0 = blockIdx.x * 128;

    for (int t = tid; t < 32 * 128; t += 256)
        sW1p[(t >> 7) * W1_STRIDE + (t & 127)] = g_w1p[t];
    for (int t = tid; t < 64 * 16; t += 256)
        sW2p[(t >> 4) * W2_STRIDE + (t & 15)] = g_w2p[t];
    if (tid < 128) sb1[tid] = b1[tid];
    for (int t = tid; t < 1024; t += 256) {
        int row = t >> 3, q = t & 7;
        int gr = row0 + row;
        uint4 v = make_uint4(0, 0, 0, 0);
        if (gr < N_NODES) v = ((const uint4*)g_aggh)[(size_t)gr * 8 + q];
        *(uint4*)((char*)sAh + row * (SA_STRIDE * 2) + q * 16) = v;
    }
    __syncthreads();

    const int lrow = l >> 2;            // 0..7
    const int colb = (l & 3) * 2;       // 0,2,4,6
    const int nb = l >> 2;
    const uint32_t a_base = su32(sAh) + (uint32_t)(((w * 16 + (l & 15)) * SA_STRIDE + ((l >> 4) * 8)) * 2);

    float acc[16][4];
    #pragma unroll
    for (int nt = 0; nt < 16; nt++)
        #pragma unroll
        for (int j = 0; j < 4; j++) acc[nt][j] = 0.f;

    #pragma unroll
    for (int kk = 0; kk < 4; kk++) {
        uint32_t a0, a1, a2, a3;
        ldmatrix4(a0, a1, a2, a3, a_base + kk * 32);
        int k2b = kk * 8 + (l & 3);
        #pragma unroll
        for (int nt = 0; nt < 16; nt++) {
            unsigned bf0 = sW1p[k2b * W1_STRIDE + nt * 8 + nb];
            unsigned bf1 = sW1p[(k2b + 4) * W1_STRIDE + nt * 8 + nb];
            mma16816(acc[nt], a0, a1, a2, a3, bf0, bf1);
        }
    }
    __syncthreads();

    // epilogue 1: bias + relu -> bf16 h tile
    const int hrow0 = w * 16 + lrow;
    #pragma unroll
    for (int nt = 0; nt < 16; nt++) {
        float bb0 = sb1[nt * 8 + colb];
        float bb1 = sb1[nt * 8 + colb + 1];
        float c0 = fmaxf(acc[nt][0] + bb0, 0.f);
        float c1 = fmaxf(acc[nt][1] + bb1, 0.f);
        float c2 = fmaxf(acc[nt][2] + bb0, 0.f);
        float c3 = fmaxf(acc[nt][3] + bb1, 0.f);
        *(unsigned*)((char*)sAh + (hrow0 * SA_STRIDE + nt * 8 + colb) * 2) = packbf(c0, c1);
        *(unsigned*)((char*)sAh + ((hrow0 + 8) * SA_STRIDE + nt * 8 + colb) * 2) = packbf(c2, c3);
    }
    __syncwarp();

    // GEMM2: h (16x128) x W2 (128x16) -> 16x16
    float acc2[2][4];
    #pragma unroll
    for (int nt = 0; nt < 2; nt++)
        #pragma unroll
        for (int j = 0; j < 4; j++) acc2[nt][j] = 0.f;

    #pragma unroll
    for (int kk = 0; kk < 8; kk++) {
        uint32_t a0, a1, a2, a3;
        ldmatrix4(a0, a1, a2, a3, a_base + kk * 32);
        int k2b = kk * 8 + (l & 3);
        #pragma unroll
        for (int nt = 0; nt < 2; nt++) {
            unsigned bf0 = sW2p[k2b * W2_STRIDE + nt * 8 + nb];
            unsigned bf1 = sW2p[(k2b + 4) * W2_STRIDE + nt * 8 + nb];
            mma16816(acc2[nt], a0, a1, a2, a3, bf0, bf1);
        }
    }

    // write z as bf16, 16-col padded rows (32B, sector-aligned)
    int gr0 = row0 + w * 16 + lrow;
    int gr1 = gr0 + 8;
    int cq = l & 3;                      // 0..3
    if (gr0 < N_NODES) {
        g_zh[(size_t)gr0 * 8 + cq] = packbf(acc2[0][0], acc2[0][1]);
        g_zh[(size_t)gr0 * 8 + 4 + cq] = (cq == 0) ? packbf(acc2[1][0], acc2[1][1]) : 0u;
    }
    if (gr1 < N_NODES) {
        g_zh[(size_t)gr1 * 8 + cq] = packbf(acc2[0][2], acc2[0][3]);
        g_zh[(size_t)gr1 * 8 + 4 + cq] = (cq == 0) ? packbf(acc2[1][2], acc2[1][3]) : 0u;
    }
}

// ---------------- K7: agg z (bf16, 1-sector/edge), log_softmax, full reduce --
__device__ __forceinline__ void acc_row(float* a, const uint4 v0, const uint2 v1, float w) {
    float2 t;
    t = unpackbf(v0.x); a[0] += w * t.x; a[1] += w * t.y;
    t = unpackbf(v0.y); a[2] += w * t.x; a[3] += w * t.y;
    t = unpackbf(v0.z); a[4] += w * t.x; a[5] += w * t.y;
    t = unpackbf(v0.w); a[6] += w * t.x; a[7] += w * t.y;
    t = unpackbf(v1.x); a[8] += w * t.x; a[9] += w * t.y;
}

__global__ void k_final(const float* __restrict__ b2, float* __restrict__ out) {
    const int tid = threadIdx.x, lane = tid & 31, wid = tid >> 5;
    int i = blockIdx.x * blockDim.x + tid;
    float vals[11];
    #pragma unroll
    for (int v = 0; v < 11; v++) vals[v] = 0.f;

    if (i < N_NODES) {
        const uint4* z4 = (const uint4*)g_zh;
        const uint2* z2 = (const uint2*)g_zh;
        float di = g_dis[i];
        float a[10];
        #pragma unroll
        for (int c = 0; c < 10; c++) a[c] = 0.f;
        acc_row(a, z4[(size_t)i * 2], z2[(size_t)i * 4 + 2], di * di);
        int p = g_ptr[i], e = g_ptr[i + 1];
        for (; p + 2 <= e; p += 2) {
            int r0 = g_srcs[p], r1 = g_srcs[p + 1];
            uint4 u0 = z4[(size_t)r0 * 2];
            uint2 w0 = z2[(size_t)r0 * 4 + 2];
            uint4 u1 = z4[(size_t)r1 * 2];
            uint2 w1 = z2[(size_t)r1 * 4 + 2];
            acc_row(a, u0, w0, g_dis[r0] * di);
            acc_row(a, u1, w1, g_dis[r1] * di);
        }
        if (p < e) {
            int r = g_srcs[p];
            acc_row(a, z4[(size_t)r * 2], z2[(size_t)r * 4 + 2], g_dis[r] * di);
        }
        float mx = -1e30f;
        #pragma unroll
        for (int c = 0; c < 10; c++) { a[c] += b2[c]; mx = fmaxf(mx, a[c]); }
        float se = 0.f;
        #pragma unroll
        for (int c = 0; c < 10; c++) se += expf(a[c] - mx);
        float lse = mx + logf(se);
        #pragma unroll
        for (int c = 0; c < 10; c++) vals[c] = a[c];
        vals[10] = lse;
    }

    #pragma unroll
    for (int v = 0; v < 11; v++)
        #pragma unroll
        for (int off = 16; off > 0; off >>= 1)
            vals[v] += __shfl_xor_sync(0xffffffffu, vals[v], off);

    __shared__ float sw[8][11];
    if (lane == 0)
        #pragma unroll
        for (int v = 0; v < 11; v++) sw[wid][v] = vals[v];
    __syncthreads();
    if (wid == 0) {
        #pragma unroll
        for (int v = 0; v < 11; v++) {
            float t = (lane < 8) ? sw[lane][v] : 0.f;
            #pragma unroll
            for (int off = 4; off > 0; off >>= 1)
                t += __shfl_xor_sync(0xffffffffu, t, off);
            if (lane == 0) g_part[blockIdx.x * 11 + v] = t;
        }
    }

    // last-block-done final reduction (deterministic: fixed summation order)
    __shared__ bool s_last;
    __threadfence();
    if (tid == 0) {
        unsigned ticket = atomicAdd(&g_done, 1u);
        s_last = (ticket == (unsigned)(gridDim.x - 1));
        if (s_last) g_done = 0;   // reset for next replay
    }
    __syncthreads();
    if (!s_last) return;

    const volatile float* vp = (const volatile float*)g_part;
    float s[11];
    #pragma unroll
    for (int v = 0; v < 11; v++) {
        float t = 0.f;
        for (int b = tid; b < NB_NODES; b += 256) t += vp[b * 11 + v];
        s[v] = t;
    }
    #pragma unroll
    for (int v = 0; v < 11; v++)
        #pragma unroll
        for (int off = 16; off > 0; off >>= 1)
            s[v] += __shfl_xor_sync(0xffffffffu, s[v], off);

    __shared__ float sw2[8][11];
    __shared__ float tot[11];
    if (lane == 0)
        #pragma unroll
        for (int v = 0; v < 11; v++) sw2[wid][v] = s[v];
    __syncthreads();
    if (wid == 0) {
        #pragma unroll
        for (int v = 0; v < 11; v++) {
            float t = (lane < 8) ? sw2[lane][v] : 0.f;
            #pragma unroll
            for (int off = 4; off > 0; off >>= 1)
                t += __shfl_xor_sync(0xffffffffu, t, off);
            if (lane == 0) tot[v] = t;
        }
    }
    __syncthreads();
    if (tid < 10) out[tid] = (tot[tid] - tot[10]) * (1.0f / (float)N_NODES);
}

// ---------------- launch ----------------
extern "C" void kernel_launch(void* const* d_in, const int* in_sizes, int n_in,
                              void* d_out, int out_size) {
    const float* x  = (const float*)d_in[0];
    const int*   ei = (const int*)d_in[1];     // edge_index: int32
    const float* W1 = (const float*)d_in[2];
    const float* b1 = (const float*)d_in[3];
    const float* W2 = (const float*)d_in[4];
    const float* b2 = (const float*)d_in[5];
    float* out = (float*)d_out;

    cudaFuncSetAttribute(k_mlp, cudaFuncAttributeMaxDynamicSharedMemorySize, SMEM_MLP);

    k_pre<<<NB_EDGES + NB_CVT + NB_W1 + NB_W2, 256>>>(ei, x, W1, W2);
    k_scan1<<<NB_NODES, 256>>>();
    k_scan23<<<NB_NODES, 256>>>();
    k_csrfill<<<NB_EDGES, 256>>>(ei);
    k_aggx<<<(N_NODES * 32 + 255) / 256, 256>>>();
    k_mlp<<<MLP_BLOCKS, 256, SMEM_MLP>>>(b1);
    k_final<<<NB_NODES, 256>>>(b2, out);
}